// round 12
// baseline (speedup 1.0000x reference)
#include <cuda_runtime.h>

#define DIM 128
#define NMAX 50000
#define EMAX 800000
#define SCAN_CHUNK 1024
#define SCAN_B ((NMAX + SCAN_CHUNK - 1) / SCAN_CHUNK)  // 49
#define GN 64   // nodes per GEMM block

// ---- static scratch (no allocation allowed) ----
__device__ __align__(16) float g_xw[(size_t)NMAX * DIM];   // x @ W
__device__ int   g_degi[NMAX];
__device__ float g_dinv[NMAX];
__device__ int   g_off[NMAX + 1];
__device__ int   g_cursor[NMAX];
__device__ int   g_csr_col[EMAX];
__device__ int   g_bsum[SCAN_B];
__device__ float g_sum[DIM];
__device__ float g_sumsq[DIM];
__device__ float g_mean[DIM];
__device__ float g_istd[DIM];

// K1: zero degree counters + BN accumulators
__global__ void k_init(int N) {
    int i = blockIdx.x * blockDim.x + threadIdx.x;
    if (i < N) g_degi[i] = 0;
    if (i < DIM) { g_sum[i] = 0.0f; g_sumsq[i] = 0.0f; }
}

// K2: count in-edges per row
__global__ void k_degree(const int* __restrict__ row, int E) {
    int e = blockIdx.x * blockDim.x + threadIdx.x;
    if (e < E) atomicAdd(&g_degi[row[e]], 1);
}

// S1: per-block degree sums + fused dinv computation
__global__ void k_scan_sum(int N) {
    __shared__ int wsum[8];
    int t = threadIdx.x;
    int base = blockIdx.x * SCAN_CHUNK + t * 4;
    int s = 0;
#pragma unroll
    for (int j = 0; j < 4; j++) {
        int i = base + j;
        if (i < N) {
            int d = g_degi[i];
            s += d;
            g_dinv[i] = rsqrtf((float)(d + 1));
        }
    }
#pragma unroll
    for (int o = 16; o > 0; o >>= 1) s += __shfl_down_sync(0xffffffffu, s, o);
    if ((t & 31) == 0) wsum[t >> 5] = s;
    __syncthreads();
    if (t == 0) {
        int tot = 0;
#pragma unroll
        for (int w = 0; w < 8; w++) tot += wsum[w];
        g_bsum[blockIdx.x] = tot;
    }
}

// S2: per-block exclusive scan + write offsets (block base computed inline)
__global__ void k_scan_write(int N, int nb) {
    __shared__ int wbase_sh[8];
    __shared__ int gbase_sh;
    int t = threadIdx.x;
    int lane = t & 31, wid = t >> 5;
    if (t == 0) {
        int gb = 0, tot = 0;
        for (int j = 0; j < nb; j++) {
            int v = g_bsum[j];
            if (j < (int)blockIdx.x) gb += v;
            tot += v;
        }
        gbase_sh = gb;
        if (blockIdx.x == 0) g_off[N] = tot;   // total = E
    }
    int base = blockIdx.x * SCAN_CHUNK + t * 4;
    int v[4];
#pragma unroll
    for (int j = 0; j < 4; j++) {
        int i = base + j;
        v[j] = (i < N) ? g_degi[i] : 0;
    }
    int tsum = v[0] + v[1] + v[2] + v[3];
    int inc = tsum;
#pragma unroll
    for (int o = 1; o < 32; o <<= 1) {
        int p = __shfl_up_sync(0xffffffffu, inc, o);
        if (lane >= o) inc += p;
    }
    if (lane == 31) wbase_sh[wid] = inc;
    __syncthreads();
    int wb = 0;
    for (int w = 0; w < wid; w++) wb += wbase_sh[w];
    int run = gbase_sh + wb + inc - tsum;
#pragma unroll
    for (int j = 0; j < 4; j++) {
        int i = base + j;
        if (i < N) {
            g_off[i] = run;
            g_cursor[i] = 0;
            run += v[j];
        }
    }
}

// K5: fill CSR (col index only; weights computed in aggregate)
__global__ void k_fill(const int* __restrict__ row,
                       const int* __restrict__ col, int E) {
    int e = blockIdx.x * blockDim.x + threadIdx.x;
    if (e >= E) return;
    int r = row[e];
    int pos = g_off[r] + atomicAdd(&g_cursor[r], 1);
    g_csr_col[pos] = col[e];
}

// K6: xw = x @ W, register-tiled with packed fma.rn.f32x2.
// Block: 64 nodes x 128 cols, 256 threads. Thread = 1 node x 32 cols
// (16 packed f32x2 accumulators). W + transposed x staged in dynamic smem.
__global__ __launch_bounds__(256) void k_gemm(const float* __restrict__ x,
                                              const float* __restrict__ W, int N) {
    extern __shared__ float sm[];
    float* ws = sm;               // [k][col]  128*128
    float* xs = sm + DIM * DIM;   // [k][node] 128*64
    int t = threadIdx.x;
    int base = blockIdx.x * GN;

    // stage W (16384 floats = 4096 float4)
    for (int i = t; i < DIM * DIM / 4; i += 256)
        reinterpret_cast<float4*>(ws)[i] = reinterpret_cast<const float4*>(W)[i];
    // stage x transposed: xs[k][node]
    for (int i = t; i < GN * DIM / 4; i += 256) {
        int n = i >> 5;             // node 0..63 (32 float4 per node)
        int kc = (i & 31) * 4;
        int gn = base + n;
        float4 v = (gn < N) ? reinterpret_cast<const float4*>(x + (size_t)gn * DIM)[i & 31]
                            : make_float4(0.f, 0.f, 0.f, 0.f);
        xs[(kc + 0) * GN + n] = v.x;
        xs[(kc + 1) * GN + n] = v.y;
        xs[(kc + 2) * GN + n] = v.z;
        xs[(kc + 3) * GN + n] = v.w;
    }
    __syncthreads();

    int lane = t & 31;
    int warp = t >> 5;
    int cgrp = warp & 3;            // 32-col group
    int ngrp = warp >> 2;           // node half
    int nloc = ngrp * 32 + lane;

    unsigned long long acc[16];
#pragma unroll
    for (int i = 0; i < 16; i++) acc[i] = 0ULL;

    const float* wbase = ws + cgrp * 32;
#pragma unroll 4
    for (int k = 0; k < DIM; k++) {
        float xv = xs[k * GN + nloc];
        unsigned long long x2;
        asm("mov.b64 %0, {%1, %1};" : "=l"(x2) : "f"(xv));
        const ulonglong2* wp = reinterpret_cast<const ulonglong2*>(wbase + k * DIM);
#pragma unroll
        for (int i = 0; i < 8; i++) {
            ulonglong2 wv = wp[i];
            asm("fma.rn.f32x2 %0, %1, %2, %0;" : "+l"(acc[2 * i])     : "l"(x2), "l"(wv.x));
            asm("fma.rn.f32x2 %0, %1, %2, %0;" : "+l"(acc[2 * i + 1]) : "l"(x2), "l"(wv.y));
        }
    }

    int gn = base + nloc;
    if (gn < N) {
        float* dst = g_xw + (size_t)gn * DIM + cgrp * 32;
#pragma unroll
        for (int i = 0; i < 8; i++) {
            float2 a  = *reinterpret_cast<float2*>(&acc[2 * i]);
            float2 b2 = *reinterpret_cast<float2*>(&acc[2 * i + 1]);
            reinterpret_cast<float4*>(dst)[i] = make_float4(a.x, a.y, b2.x, b2.y);
        }
    }
}

// K7: gather-aggregate + fused BN stats. dinv[r] factored out of edge sum:
// out[r] = dinv[r]*(dinv[r]*xw[r] + sum_e dinv[c_e]*xw[c_e]) + b
__global__ void k_aggregate(float* __restrict__ out, const float* __restrict__ b, int N) {
    __shared__ float s_sum[DIM];
    __shared__ float s_sq[DIM];
    int t = threadIdx.x;
    if (t < DIM) { s_sum[t] = 0.0f; s_sq[t] = 0.0f; }
    __syncthreads();

    int warp = (blockIdx.x * blockDim.x + t) >> 5;
    int lane = t & 31;
    const float4* xw4 = reinterpret_cast<const float4*>(g_xw);

    if (warp < N) {
        int r = warp;
        float di = g_dinv[r];
        float4 selfv = xw4[(size_t)r * 32 + lane];
        float4 es = make_float4(0.f, 0.f, 0.f, 0.f);

        int k0 = g_off[r], k1 = g_off[r + 1];
        int k = k0;
        for (; k + 1 < k1; k += 2) {
            int c0 = g_csr_col[k];
            int c1 = g_csr_col[k + 1];
            float w0 = g_dinv[c0];
            float w1 = g_dinv[c1];
            float4 v0 = xw4[(size_t)c0 * 32 + lane];
            float4 v1 = xw4[(size_t)c1 * 32 + lane];
            es.x = fmaf(v0.x, w0, es.x); es.y = fmaf(v0.y, w0, es.y);
            es.z = fmaf(v0.z, w0, es.z); es.w = fmaf(v0.w, w0, es.w);
            es.x = fmaf(v1.x, w1, es.x); es.y = fmaf(v1.y, w1, es.y);
            es.z = fmaf(v1.z, w1, es.z); es.w = fmaf(v1.w, w1, es.w);
        }
        if (k < k1) {
            int c = g_csr_col[k]; float w = g_dinv[c];
            float4 v = xw4[(size_t)c * 32 + lane];
            es.x = fmaf(v.x, w, es.x); es.y = fmaf(v.y, w, es.y);
            es.z = fmaf(v.z, w, es.z); es.w = fmaf(v.w, w, es.w);
        }

        float4 bb = reinterpret_cast<const float4*>(b)[lane];
        float4 acc;
        acc.x = fmaf(fmaf(selfv.x, di, es.x), di, bb.x);
        acc.y = fmaf(fmaf(selfv.y, di, es.y), di, bb.y);
        acc.z = fmaf(fmaf(selfv.z, di, es.z), di, bb.z);
        acc.w = fmaf(fmaf(selfv.w, di, es.w), di, bb.w);
        reinterpret_cast<float4*>(out)[(size_t)warp * 32 + lane] = acc;

        int c0 = lane * 4;
        atomicAdd(&s_sum[c0 + 0], acc.x); atomicAdd(&s_sq[c0 + 0], acc.x * acc.x);
        atomicAdd(&s_sum[c0 + 1], acc.y); atomicAdd(&s_sq[c0 + 1], acc.y * acc.y);
        atomicAdd(&s_sum[c0 + 2], acc.z); atomicAdd(&s_sq[c0 + 2], acc.z * acc.z);
        atomicAdd(&s_sum[c0 + 3], acc.w); atomicAdd(&s_sq[c0 + 3], acc.w * acc.w);
    }
    __syncthreads();
    if (t < DIM) {
        atomicAdd(&g_sum[t], s_sum[t]);
        atomicAdd(&g_sumsq[t], s_sq[t]);
    }
}

// K8: finalize mean / inv-std
__global__ void k_finstats(int N) {
    int j = threadIdx.x;
    float invN = 1.0f / (float)N;
    float m = g_sum[j] * invN;
    float var = g_sumsq[j] * invN - m * m;
    g_mean[j] = m;
    g_istd[j] = rsqrtf(var + 1e-5f);
}

// K9: y = relu((out - mean) * istd * gamma + beta) + x
__global__ void k_final(float* __restrict__ out, const float* __restrict__ x,
                        const float* __restrict__ gamma, const float* __restrict__ beta,
                        int nvec) {
    int idx = blockIdx.x * blockDim.x + threadIdx.x;
    if (idx >= nvec) return;
    int c = (idx & 31) * 4;
    float4 v = reinterpret_cast<float4*>(out)[idx];
    float4 xv = reinterpret_cast<const float4*>(x)[idx];
    float4 y;
    y.x = fmaxf((v.x - g_mean[c + 0]) * g_istd[c + 0] * gamma[c + 0] + beta[c + 0], 0.0f) + xv.x;
    y.y = fmaxf((v.y - g_mean[c + 1]) * g_istd[c + 1] * gamma[c + 1] + beta[c + 1], 0.0f) + xv.y;
    y.z = fmaxf((v.z - g_mean[c + 2]) * g_istd[c + 2] * gamma[c + 2] + beta[c + 2], 0.0f) + xv.z;
    y.w = fmaxf((v.w - g_mean[c + 3]) * g_istd[c + 3] * gamma[c + 3] + beta[c + 3], 0.0f) + xv.w;
    reinterpret_cast<float4*>(out)[idx] = y;
}

extern "C" void kernel_launch(void* const* d_in, const int* in_sizes, int n_in,
                              void* d_out, int out_size) {
    const float* x     = (const float*)d_in[0];
    const int*   ei    = (const int*)d_in[1];   // int32 edge indices
    const float* W     = (const float*)d_in[2];
    const float* b     = (const float*)d_in[3];
    const float* gamma = (const float*)d_in[4];
    const float* beta  = (const float*)d_in[5];
    float* out = (float*)d_out;

    int N = in_sizes[0] / DIM;         // 50000
    int E = in_sizes[1] / 2;           // 800000
    const int* row = ei;
    const int* col = ei + E;
    int nvec = N * (DIM / 4);
    int nb_scan = (N + SCAN_CHUNK - 1) / SCAN_CHUNK;   // 49
    int smem_gemm = (DIM * DIM + DIM * GN) * (int)sizeof(float);  // 96KB

    static int configured = 0;
    if (!configured) {
        cudaFuncSetAttribute(k_gemm, cudaFuncAttributeMaxDynamicSharedMemorySize, smem_gemm);
        configured = 1;
    }

    k_init<<<(N + 255) / 256, 256>>>(N);
    k_degree<<<(E + 255) / 256, 256>>>(row, E);
    k_scan_sum<<<nb_scan, 256>>>(N);
    k_scan_write<<<nb_scan, 256>>>(N, nb_scan);
    k_fill<<<(E + 255) / 256, 256>>>(row, col, E);
    k_gemm<<<(N + GN - 1) / GN, 256, smem_gemm>>>(x, W, N);
    k_aggregate<<<(N * 32 + 255) / 256, 256>>>(out, b, N);
    k_finstats<<<1, DIM>>>(N);
    k_final<<<(nvec + 255) / 256, 256>>>(out, x, gamma, beta, nvec);
}

// round 13
// speedup vs baseline: 1.0739x; 1.0739x over previous
#include <cuda_runtime.h>

#define DIM 128
#define NMAX 50000
#define EMAX 800000
#define SCAN_CHUNK 1024
#define SCAN_B ((NMAX + SCAN_CHUNK - 1) / SCAN_CHUNK)  // 49
#define GN 64   // nodes per GEMM block

// ---- static scratch (no allocation allowed) ----
__device__ __align__(16) float g_xw[(size_t)NMAX * DIM];   // x @ W
__device__ int   g_degi[NMAX];
__device__ float g_dinv[NMAX];
__device__ int   g_off[NMAX + 1];
__device__ int   g_cursor[NMAX];
__device__ int   g_csr_col[EMAX];
__device__ float g_csr_w[EMAX];       // precomputed dinv[r]*dinv[c] (coalesced stream)
__device__ int   g_bsum[SCAN_B];
__device__ float g_sum[DIM];
__device__ float g_sumsq[DIM];
__device__ float g_mean[DIM];
__device__ float g_istd[DIM];

// K1: zero degree counters + BN accumulators
__global__ void k_init(int N) {
    int i = blockIdx.x * blockDim.x + threadIdx.x;
    if (i < N) g_degi[i] = 0;
    if (i < DIM) { g_sum[i] = 0.0f; g_sumsq[i] = 0.0f; }
}

// K2: count in-edges per row
__global__ void k_degree(const int* __restrict__ row, int E) {
    int e = blockIdx.x * blockDim.x + threadIdx.x;
    if (e < E) atomicAdd(&g_degi[row[e]], 1);
}

// S1: per-block degree sums + fused dinv computation
__global__ void k_scan_sum(int N) {
    __shared__ int wsum[8];
    int t = threadIdx.x;
    int base = blockIdx.x * SCAN_CHUNK + t * 4;
    int s = 0;
#pragma unroll
    for (int j = 0; j < 4; j++) {
        int i = base + j;
        if (i < N) {
            int d = g_degi[i];
            s += d;
            g_dinv[i] = rsqrtf((float)(d + 1));
        }
    }
#pragma unroll
    for (int o = 16; o > 0; o >>= 1) s += __shfl_down_sync(0xffffffffu, s, o);
    if ((t & 31) == 0) wsum[t >> 5] = s;
    __syncthreads();
    if (t == 0) {
        int tot = 0;
#pragma unroll
        for (int w = 0; w < 8; w++) tot += wsum[w];
        g_bsum[blockIdx.x] = tot;
    }
}

// S2: per-block exclusive scan + write offsets.
// Block base: stage g_bsum into shared in parallel, then cheap serial scan.
__global__ void k_scan_write(int N, int nb) {
    __shared__ int wbase_sh[8];
    __shared__ int bsum_sh[SCAN_B];
    __shared__ int gbase_sh;
    int t = threadIdx.x;
    int lane = t & 31, wid = t >> 5;
    if (t < nb) bsum_sh[t] = g_bsum[t];
    __syncthreads();
    if (t == 0) {
        int gb = 0, tot = 0;
        for (int j = 0; j < nb; j++) {
            int v = bsum_sh[j];
            if (j < (int)blockIdx.x) gb += v;
            tot += v;
        }
        gbase_sh = gb;
        if (blockIdx.x == 0) g_off[N] = tot;   // total = E
    }
    int base = blockIdx.x * SCAN_CHUNK + t * 4;
    int v[4];
#pragma unroll
    for (int j = 0; j < 4; j++) {
        int i = base + j;
        v[j] = (i < N) ? g_degi[i] : 0;
    }
    int tsum = v[0] + v[1] + v[2] + v[3];
    int inc = tsum;
#pragma unroll
    for (int o = 1; o < 32; o <<= 1) {
        int p = __shfl_up_sync(0xffffffffu, inc, o);
        if (lane >= o) inc += p;
    }
    if (lane == 31) wbase_sh[wid] = inc;
    __syncthreads();
    int wb = 0;
    for (int w = 0; w < wid; w++) wb += wbase_sh[w];
    int run = gbase_sh + wb + inc - tsum;
#pragma unroll
    for (int j = 0; j < 4; j++) {
        int i = base + j;
        if (i < N) {
            g_off[i] = run;
            g_cursor[i] = 0;
            run += v[j];
        }
    }
}

// K5: fill CSR — col index AND precomputed weight (restores coalesced w stream)
__global__ void k_fill(const int* __restrict__ row,
                       const int* __restrict__ col, int E) {
    int e = blockIdx.x * blockDim.x + threadIdx.x;
    if (e >= E) return;
    int r = row[e];
    int c = col[e];
    int pos = g_off[r] + atomicAdd(&g_cursor[r], 1);
    g_csr_col[pos] = c;
    g_csr_w[pos] = g_dinv[r] * g_dinv[c];
}

// K6: xw = x @ W, register-tiled with packed fma.rn.f32x2.
// Block: 64 nodes x 128 cols, 256 threads. Thread = 1 node x 32 cols.
// Staging mapping fixed: lanes write consecutive n -> conflict-free STS.
__global__ __launch_bounds__(256) void k_gemm(const float* __restrict__ x,
                                              const float* __restrict__ W, int N) {
    extern __shared__ float sm[];
    float* ws = sm;               // [k][col]  128*128
    float* xs = sm + DIM * DIM;   // [k][node] 128*64
    int t = threadIdx.x;
    int base = blockIdx.x * GN;

    // stage W (16384 floats = 4096 float4), coalesced
    for (int i = t; i < DIM * DIM / 4; i += 256)
        reinterpret_cast<float4*>(ws)[i] = reinterpret_cast<const float4*>(W)[i];

    // stage x transposed, conflict-free: thread t -> node n = t&63, kc-quarter = t>>6
    {
        int n = t & 63;
        int q = t >> 6;            // 0..3 -> cols q*32 .. q*32+31
        int gn = base + n;
#pragma unroll
        for (int j = 0; j < 8; j++) {
            int kc = q * 32 + j * 4;
            float4 v = (gn < N)
                ? reinterpret_cast<const float4*>(x + (size_t)gn * DIM)[kc >> 2]
                : make_float4(0.f, 0.f, 0.f, 0.f);
            xs[(kc + 0) * GN + n] = v.x;   // lanes: consecutive n -> no conflict
            xs[(kc + 1) * GN + n] = v.y;
            xs[(kc + 2) * GN + n] = v.z;
            xs[(kc + 3) * GN + n] = v.w;
        }
    }
    __syncthreads();

    int lane = t & 31;
    int warp = t >> 5;
    int cgrp = warp & 3;            // 32-col group
    int ngrp = warp >> 2;           // node half
    int nloc = ngrp * 32 + lane;

    unsigned long long acc[16];
#pragma unroll
    for (int i = 0; i < 16; i++) acc[i] = 0ULL;

    const float* wbase = ws + cgrp * 32;
#pragma unroll 4
    for (int k = 0; k < DIM; k++) {
        float xv = xs[k * GN + nloc];
        unsigned long long x2;
        asm("mov.b64 %0, {%1, %1};" : "=l"(x2) : "f"(xv));
        const ulonglong2* wp = reinterpret_cast<const ulonglong2*>(wbase + k * DIM);
#pragma unroll
        for (int i = 0; i < 8; i++) {
            ulonglong2 wv = wp[i];
            asm("fma.rn.f32x2 %0, %1, %2, %0;" : "+l"(acc[2 * i])     : "l"(x2), "l"(wv.x));
            asm("fma.rn.f32x2 %0, %1, %2, %0;" : "+l"(acc[2 * i + 1]) : "l"(x2), "l"(wv.y));
        }
    }

    int gn = base + nloc;
    if (gn < N) {
        float* dst = g_xw + (size_t)gn * DIM + cgrp * 32;
#pragma unroll
        for (int i = 0; i < 8; i++) {
            float2 a  = *reinterpret_cast<float2*>(&acc[2 * i]);
            float2 b2 = *reinterpret_cast<float2*>(&acc[2 * i + 1]);
            reinterpret_cast<float4*>(dst)[i] = make_float4(a.x, a.y, b2.x, b2.y);
        }
    }
}

// K7: gather-aggregate + fused BN stats (R11 hot loop: coalesced csr_w stream)
__global__ void k_aggregate(float* __restrict__ out, const float* __restrict__ b, int N) {
    __shared__ float s_sum[DIM];
    __shared__ float s_sq[DIM];
    int t = threadIdx.x;
    if (t < DIM) { s_sum[t] = 0.0f; s_sq[t] = 0.0f; }
    __syncthreads();

    int warp = (blockIdx.x * blockDim.x + t) >> 5;
    int lane = t & 31;
    const float4* xw4 = reinterpret_cast<const float4*>(g_xw);

    if (warp < N) {
        int r = warp;
        float di = g_dinv[r];
        float s = di * di;
        float4 acc = xw4[(size_t)r * 32 + lane];   // self loop
        acc.x *= s; acc.y *= s; acc.z *= s; acc.w *= s;

        int k0 = g_off[r], k1 = g_off[r + 1];
        int k = k0;
        for (; k + 1 < k1; k += 2) {
            int c0 = g_csr_col[k];     float w0 = g_csr_w[k];
            int c1 = g_csr_col[k + 1]; float w1 = g_csr_w[k + 1];
            float4 v0 = xw4[(size_t)c0 * 32 + lane];
            float4 v1 = xw4[(size_t)c1 * 32 + lane];
            acc.x = fmaf(v0.x, w0, acc.x); acc.y = fmaf(v0.y, w0, acc.y);
            acc.z = fmaf(v0.z, w0, acc.z); acc.w = fmaf(v0.w, w0, acc.w);
            acc.x = fmaf(v1.x, w1, acc.x); acc.y = fmaf(v1.y, w1, acc.y);
            acc.z = fmaf(v1.z, w1, acc.z); acc.w = fmaf(v1.w, w1, acc.w);
        }
        if (k < k1) {
            int c = g_csr_col[k]; float w = g_csr_w[k];
            float4 v = xw4[(size_t)c * 32 + lane];
            acc.x = fmaf(v.x, w, acc.x); acc.y = fmaf(v.y, w, acc.y);
            acc.z = fmaf(v.z, w, acc.z); acc.w = fmaf(v.w, w, acc.w);
        }

        float4 bb = reinterpret_cast<const float4*>(b)[lane];
        acc.x += bb.x; acc.y += bb.y; acc.z += bb.z; acc.w += bb.w;
        reinterpret_cast<float4*>(out)[(size_t)warp * 32 + lane] = acc;

        int c0 = lane * 4;
        atomicAdd(&s_sum[c0 + 0], acc.x); atomicAdd(&s_sq[c0 + 0], acc.x * acc.x);
        atomicAdd(&s_sum[c0 + 1], acc.y); atomicAdd(&s_sq[c0 + 1], acc.y * acc.y);
        atomicAdd(&s_sum[c0 + 2], acc.z); atomicAdd(&s_sq[c0 + 2], acc.z * acc.z);
        atomicAdd(&s_sum[c0 + 3], acc.w); atomicAdd(&s_sq[c0 + 3], acc.w * acc.w);
    }
    __syncthreads();
    if (t < DIM) {
        atomicAdd(&g_sum[t], s_sum[t]);
        atomicAdd(&g_sumsq[t], s_sq[t]);
    }
}

// K8: finalize mean / inv-std
__global__ void k_finstats(int N) {
    int j = threadIdx.x;
    float invN = 1.0f / (float)N;
    float m = g_sum[j] * invN;
    float var = g_sumsq[j] * invN - m * m;
    g_mean[j] = m;
    g_istd[j] = rsqrtf(var + 1e-5f);
}

// K9: y = relu((out - mean) * istd * gamma + beta) + x
__global__ void k_final(float* __restrict__ out, const float* __restrict__ x,
                        const float* __restrict__ gamma, const float* __restrict__ beta,
                        int nvec) {
    int idx = blockIdx.x * blockDim.x + threadIdx.x;
    if (idx >= nvec) return;
    int c = (idx & 31) * 4;
    float4 v = reinterpret_cast<float4*>(out)[idx];
    float4 xv = reinterpret_cast<const float4*>(x)[idx];
    float4 y;
    y.x = fmaxf((v.x - g_mean[c + 0]) * g_istd[c + 0] * gamma[c + 0] + beta[c + 0], 0.0f) + xv.x;
    y.y = fmaxf((v.y - g_mean[c + 1]) * g_istd[c + 1] * gamma[c + 1] + beta[c + 1], 0.0f) + xv.y;
    y.z = fmaxf((v.z - g_mean[c + 2]) * g_istd[c + 2] * gamma[c + 2] + beta[c + 2], 0.0f) + xv.z;
    y.w = fmaxf((v.w - g_mean[c + 3]) * g_istd[c + 3] * gamma[c + 3] + beta[c + 3], 0.0f) + xv.w;
    reinterpret_cast<float4*>(out)[idx] = y;
}

extern "C" void kernel_launch(void* const* d_in, const int* in_sizes, int n_in,
                              void* d_out, int out_size) {
    const float* x     = (const float*)d_in[0];
    const int*   ei    = (const int*)d_in[1];   // int32 edge indices
    const float* W     = (const float*)d_in[2];
    const float* b     = (const float*)d_in[3];
    const float* gamma = (const float*)d_in[4];
    const float* beta  = (const float*)d_in[5];
    float* out = (float*)d_out;

    int N = in_sizes[0] / DIM;         // 50000
    int E = in_sizes[1] / 2;           // 800000
    const int* row = ei;
    const int* col = ei + E;
    int nvec = N * (DIM / 4);
    int nb_scan = (N + SCAN_CHUNK - 1) / SCAN_CHUNK;   // 49
    int smem_gemm = (DIM * DIM + DIM * GN) * (int)sizeof(float);  // 96KB

    static int configured = 0;
    if (!configured) {
        cudaFuncSetAttribute(k_gemm, cudaFuncAttributeMaxDynamicSharedMemorySize, smem_gemm);
        configured = 1;
    }

    k_init<<<(N + 255) / 256, 256>>>(N);
    k_degree<<<(E + 255) / 256, 256>>>(row, E);
    k_scan_sum<<<nb_scan, 256>>>(N);
    k_scan_write<<<nb_scan, 256>>>(N, nb_scan);
    k_fill<<<(E + 255) / 256, 256>>>(row, col, E);
    k_gemm<<<(N + GN - 1) / GN, 256, smem_gemm>>>(x, W, N);
    k_aggregate<<<(N * 32 + 255) / 256, 256>>>(out, b, N);
    k_finstats<<<1, DIM>>>(N);
    k_final<<<(nvec + 255) / 256, 256>>>(out, x, gamma, beta, nvec);
}